// round 1
// baseline (speedup 1.0000x reference)
#include <cuda_runtime.h>
#include <math.h>

// NT-Xent loss, fused: normalize -> streaming GEMM+exp+rowsum -> log reduce.
// Round 1: fp32 SIMT baseline (correctness anchor). Tensor-core (tcgen05)
// conversion planned once baseline + profile are in hand.

#define NROWS 8192
#define NC    512
#define BHALF 4096
#define INV_TAU 10.0f

#define BM 64
#define BN 128
#define BK 16
#define NQUAD 4
#define COLS_PER (NROWS / NQUAD)   // 2048

// Scratch (static __device__ globals per allocation rules)
__device__ float g_zn[(size_t)NROWS * NC];          // normalized z, fp32 (16 MB)
__device__ float g_pos[NROWS];                      // exp(pos/tau) per row
__device__ float g_rowsum[NQUAD * NROWS];           // partial row sums per col-quarter

// ---------------------------------------------------------------------------
// Kernel 1: L2-normalize rows of z1 (rows 0..4095) and z2 (rows 4096..8191).
// One block per row, 128 threads, 4 elems/thread.
// ---------------------------------------------------------------------------
__global__ void normalize_kernel(const float* __restrict__ z1,
                                 const float* __restrict__ z2) {
    int r = blockIdx.x;
    const float* src = (r < BHALF) ? (z1 + (size_t)r * NC)
                                   : (z2 + (size_t)(r - BHALF) * NC);
    int t = threadIdx.x;
    float v[4];
    float s = 0.f;
#pragma unroll
    for (int i = 0; i < 4; i++) {
        v[i] = src[t + i * 128];
        s += v[i] * v[i];
    }
#pragma unroll
    for (int o = 16; o; o >>= 1) s += __shfl_xor_sync(0xFFFFFFFFu, s, o);
    __shared__ float ws[4];
    if ((t & 31) == 0) ws[t >> 5] = s;
    __syncthreads();
    s = ws[0] + ws[1] + ws[2] + ws[3];
    float inv = 1.0f / fmaxf(sqrtf(s), 1e-12f);
#pragma unroll
    for (int i = 0; i < 4; i++)
        g_zn[(size_t)r * NC + t + i * 128] = v[i] * inv;
}

// ---------------------------------------------------------------------------
// Kernel 2: For each row r, accumulate sum_c exp(dot(z_r, z_c)/tau) over the
// block's column quarter, and capture the positive entry exp(dot(z_r,z_{r+B}))
// when it falls in this block's tile.
// BM=64 rows/block, BN=128 col tile, BK=16, 128 threads, 8x8 microtile.
// Grid: (NROWS/BM = 128, NQUAD = 4) = 512 blocks -> single wave @ 4 blocks/SM.
// ---------------------------------------------------------------------------
__global__ __launch_bounds__(128, 4) void gemm_rowsum_kernel() {
    __shared__ float sA[BK][BM];     // 4 KB
    __shared__ float sB[BK][BN];     // 8 KB
    __shared__ float red[BM][16];    // 4 KB

    int tid = threadIdx.x;
    int tx = tid & 15;   // 0..15 -> 8 cols each
    int ty = tid >> 4;   // 0..7  -> 8 rows each
    int r0 = blockIdx.x * BM;
    int cbase = blockIdx.y * COLS_PER;

    float rsum[8];
#pragma unroll
    for (int i = 0; i < 8; i++) rsum[i] = 0.f;

    for (int ct = 0; ct < COLS_PER / BN; ct++) {
        int c0 = cbase + ct * BN;

        float acc[8][8];
#pragma unroll
        for (int i = 0; i < 8; i++)
#pragma unroll
            for (int j = 0; j < 8; j++) acc[i][j] = 0.f;

        for (int kt = 0; kt < NC / BK; kt++) {
            int k0 = kt * BK;
            // Load A tile: 64x16 floats = 256 float4, 2 per thread
#pragma unroll
            for (int it = 0; it < 2; it++) {
                int idx = tid + it * 128;          // 0..255
                int m = idx >> 2;                  // 0..63
                int kq = (idx & 3) * 4;            // 0,4,8,12
                float4 f = *(const float4*)&g_zn[(size_t)(r0 + m) * NC + k0 + kq];
                sA[kq + 0][m] = f.x; sA[kq + 1][m] = f.y;
                sA[kq + 2][m] = f.z; sA[kq + 3][m] = f.w;
            }
            // Load B tile: 128x16 floats = 512 float4, 4 per thread
#pragma unroll
            for (int it = 0; it < 4; it++) {
                int idx = tid + it * 128;          // 0..511
                int n = idx >> 2;                  // 0..127
                int kq = (idx & 3) * 4;
                float4 f = *(const float4*)&g_zn[(size_t)(c0 + n) * NC + k0 + kq];
                sB[kq + 0][n] = f.x; sB[kq + 1][n] = f.y;
                sB[kq + 2][n] = f.z; sB[kq + 3][n] = f.w;
            }
            __syncthreads();
#pragma unroll
            for (int k = 0; k < BK; k++) {
                float a[8], b[8];
                *(float4*)&a[0] = *(const float4*)&sA[k][ty * 8];
                *(float4*)&a[4] = *(const float4*)&sA[k][ty * 8 + 4];
                *(float4*)&b[0] = *(const float4*)&sB[k][tx * 8];
                *(float4*)&b[4] = *(const float4*)&sB[k][tx * 8 + 4];
#pragma unroll
                for (int i = 0; i < 8; i++)
#pragma unroll
                    for (int j = 0; j < 8; j++)
                        acc[i][j] += a[i] * b[j];
            }
            __syncthreads();
        }

        // Epilogue: exp + rowsum accumulation + positive capture
#pragma unroll
        for (int i = 0; i < 8; i++) {
            int gr = r0 + ty * 8 + i;
            int pc = (gr + BHALF) & (NROWS - 1);
#pragma unroll
            for (int j = 0; j < 8; j++) {
                float e = __expf(acc[i][j] * INV_TAU);
                rsum[i] += e;
                int gc = c0 + tx * 8 + j;
                if (gc == pc) g_pos[gr] = e;   // exactly one writer per row
            }
        }
    }

    // Reduce rsum across the 16 tx-threads sharing each row
    __syncthreads();
#pragma unroll
    for (int i = 0; i < 8; i++) red[ty * 8 + i][tx] = rsum[i];
    __syncthreads();
    if (tid < BM) {
        float s = 0.f;
#pragma unroll
        for (int t = 0; t < 16; t++) s += red[tid][t];
        g_rowsum[blockIdx.y * NROWS + r0 + tid] = s;
    }
}

// ---------------------------------------------------------------------------
// Kernel 3: final scalar loss = sum_r [log(rowsum_r - pos_r) - log(pos_r)]
//           / (NROWS * BHALF)
// ---------------------------------------------------------------------------
__global__ void loss_kernel(float* __restrict__ out) {
    __shared__ float ws[8];
    float s = 0.f;
    for (int r = threadIdx.x; r < NROWS; r += blockDim.x) {
        float tot = g_rowsum[r] + g_rowsum[NROWS + r] +
                    g_rowsum[2 * NROWS + r] + g_rowsum[3 * NROWS + r];
        float p = g_pos[r];
        s += logf(tot - p) - logf(p);
    }
#pragma unroll
    for (int o = 16; o; o >>= 1) s += __shfl_xor_sync(0xFFFFFFFFu, s, o);
    if ((threadIdx.x & 31) == 0) ws[threadIdx.x >> 5] = s;
    __syncthreads();
    if (threadIdx.x < 8) {
        float v = ws[threadIdx.x];
#pragma unroll
        for (int o = 4; o; o >>= 1) v += __shfl_xor_sync(0xFFu, v, o);
        if (threadIdx.x == 0)
            out[0] = v / ((float)NROWS * (float)BHALF);
    }
}

extern "C" void kernel_launch(void* const* d_in, const int* in_sizes, int n_in,
                              void* d_out, int out_size) {
    const float* z1 = (const float*)d_in[0];
    const float* z2 = (const float*)d_in[1];
    (void)in_sizes; (void)n_in; (void)out_size;

    normalize_kernel<<<NROWS, 128>>>(z1, z2);
    dim3 grid(NROWS / BM, NQUAD);
    gemm_rowsum_kernel<<<grid, 128>>>();
    loss_kernel<<<1, 256>>>((float*)d_out);
}

// round 3
// speedup vs baseline: 4.5031x; 4.5031x over previous
#include <cuda_runtime.h>
#include <cuda_bf16.h>
#include <math.h>
#include <stdint.h>

// NT-Xent loss on GB300 via baseline-PTX tensor cores (mma.sync HMMA):
//   normalize (fp32 -> bf16 unit rows) ->
//   tiled bf16 GEMM S = z z^T with fused exp/rowsum epilogue (S never stored) ->
//   log reduce.
// tcgen05 is unavailable (harness PTX targets compute_103, not 103a), so we
// use mma.sync.m16n8k16 which is baseline PTX.

#define NROWS 8192
#define NC    512
#define BHALF 4096

#define BM 128
#define BN 128
#define BK 64
#define KITERS (NC / BK)        // 8
#define NSTAGE 3
#define STAGE_BYTES (2 * BM * BK * 2)   // A + B = 32768
#define SMEM_TOTAL (NSTAGE * STAGE_BYTES)  // 98304

__device__ __align__(1024) __nv_bfloat16 g_zn[(size_t)NROWS * NC];
__device__ float g_pos[NROWS];
__device__ float g_rs[(size_t)NROWS * 64];   // per-row partial rowsums, [row][bn]

__device__ __forceinline__ uint32_t smem_u32(const void* p) {
    uint32_t a;
    asm("{ .reg .u64 t; cvta.to.shared.u64 t, %1; cvt.u32.u64 %0, t; }"
        : "=r"(a) : "l"(p));
    return a;
}

#define CP_ASYNC16(dst, src) \
    asm volatile("cp.async.cg.shared.global [%0], [%1], 16;" :: "r"(dst), "l"(src) : "memory")
#define CP_COMMIT() asm volatile("cp.async.commit_group;" ::: "memory")

#define LDSM_X4(r0, r1, r2, r3, addr)                                          \
    asm volatile("ldmatrix.sync.aligned.m8n8.x4.shared.b16 {%0,%1,%2,%3}, [%4];" \
                 : "=r"(r0), "=r"(r1), "=r"(r2), "=r"(r3) : "r"(addr))

#define MMA16816(c, a0, a1, a2, a3, b0, b1)                                    \
    asm volatile("mma.sync.aligned.m16n8k16.row.col.f32.bf16.bf16.f32 "        \
                 "{%0,%1,%2,%3},{%4,%5,%6,%7},{%8,%9},{%0,%1,%2,%3};"          \
                 : "+f"((c)[0]), "+f"((c)[1]), "+f"((c)[2]), "+f"((c)[3])      \
                 : "r"(a0), "r"(a1), "r"(a2), "r"(a3), "r"(b0), "r"(b1))

// ---------------------------------------------------------------------------
// Kernel 1: L2-normalize rows, emit bf16 z (z1 -> rows 0..4095, z2 -> rest)
// ---------------------------------------------------------------------------
__global__ void normalize_kernel(const float* __restrict__ z1,
                                 const float* __restrict__ z2) {
    int r = blockIdx.x;
    const float* row = (r < BHALF) ? (z1 + (size_t)r * NC)
                                   : (z2 + (size_t)(r - BHALF) * NC);
    int t = threadIdx.x;  // 128 threads, float4 each
    float4 v = ((const float4*)row)[t];
    float s = v.x * v.x + v.y * v.y + v.z * v.z + v.w * v.w;
#pragma unroll
    for (int o = 16; o; o >>= 1) s += __shfl_xor_sync(0xFFFFFFFFu, s, o);
    __shared__ float ws[4];
    if ((t & 31) == 0) ws[t >> 5] = s;
    __syncthreads();
    s = ws[0] + ws[1] + ws[2] + ws[3];
    float inv = 1.0f / fmaxf(sqrtf(s), 1e-12f);
    __nv_bfloat162 lo = __floats2bfloat162_rn(v.x * inv, v.y * inv);
    __nv_bfloat162 hi = __floats2bfloat162_rn(v.z * inv, v.w * inv);
    __nv_bfloat162* dst = (__nv_bfloat162*)g_zn + (size_t)r * (NC / 2) + t * 2;
    dst[0] = lo;
    dst[1] = hi;
}

// ---------------------------------------------------------------------------
// Kernel 2: fused GEMM + exp + rowsum + positive capture.
// Grid (64, 64): blockIdx.x = bn (column tile), blockIdx.y = bm (row tile).
// 256 threads = 8 warps in 2(M) x 4(N); warp tile 64x32 via m16n8k16.
// ---------------------------------------------------------------------------
__global__ __launch_bounds__(256, 1) void gemm_kernel() {
    extern __shared__ __align__(1024) char smem[];
    const int tid = threadIdx.x;
    const int lane = tid & 31;
    const int w = tid >> 5;
    const int wm = w >> 2;       // 0..1
    const int wn = w & 3;        // 0..3
    const int bn = blockIdx.x;
    const int bm = blockIdx.y;
    const int r0 = bm * BM;
    const int c0 = bn * BN;
    const uint32_t sbase = smem_u32(smem);

    // ---- cp.async mapping: 256 threads -> 256 tile rows (128 A + 128 B) ----
    const int half = tid >> 7;          // 0 = A, 1 = B
    const int lrow = tid & 127;
    const char* grow = (const char*)g_zn +
        ((size_t)((half ? c0 : r0) + lrow)) * (NC * 2);
    const uint32_t sdst = sbase + (uint32_t)half * (BM * BK * 2) +
                          (uint32_t)lrow * 128u;
    const uint32_t xr = ((uint32_t)lrow & 7u) << 4;

#define ISSUE_STAGE(s_)                                                        \
    do {                                                                       \
        const char* g_ = grow + (s_) * (BK * 2);                               \
        uint32_t d_ = sdst + (uint32_t)((s_) % NSTAGE) * STAGE_BYTES;          \
        _Pragma("unroll")                                                      \
        for (int c_ = 0; c_ < 8; c_++)                                         \
            CP_ASYNC16(d_ + (((uint32_t)c_ * 16u) ^ xr), g_ + c_ * 16);        \
        CP_COMMIT();                                                           \
    } while (0)

    ISSUE_STAGE(0);
    ISSUE_STAGE(1);

    // ---- ldmatrix address precompute ----
    // A: x4 tile = m16 x k16. lane 0-15 -> rows, lane>>4 -> k-chunk (16B).
    uint32_t addrA[4], xA[4];
    const uint32_t chunkA = ((uint32_t)(lane >> 4)) * 16u;
#pragma unroll
    for (int mi = 0; mi < 4; mi++) {
        int rA = wm * 64 + mi * 16 + (lane & 15);
        addrA[mi] = sbase + (uint32_t)rA * 128u;
        xA[mi] = ((uint32_t)rA & 7u) << 4;
    }
    // B: x4 tile = two n8 x k16 tiles. lane>>3 = matrix id:
    //   bit0 -> k-chunk, bit1 -> +8 n-rows.
    uint32_t addrB[2], xB[2];
    const uint32_t chunkB = ((uint32_t)((lane >> 3) & 1)) * 16u;
#pragma unroll
    for (int np = 0; np < 2; np++) {
        int rB = wn * 32 + np * 16 + ((lane >> 4) & 1) * 8 + (lane & 7);
        addrB[np] = sbase + (uint32_t)(BM * BK * 2) + (uint32_t)rB * 128u;
        xB[np] = ((uint32_t)rB & 7u) << 4;
    }

    float acc[4][4][4];
#pragma unroll
    for (int mi = 0; mi < 4; mi++)
#pragma unroll
        for (int ni = 0; ni < 4; ni++)
#pragma unroll
            for (int e = 0; e < 4; e++) acc[mi][ni][e] = 0.f;

    // ---- mainloop ----
#pragma unroll 1
    for (int i = 0; i < KITERS; i++) {
        if (i < KITERS - 1)
            asm volatile("cp.async.wait_group 1;" ::: "memory");
        else
            asm volatile("cp.async.wait_group 0;" ::: "memory");
        __syncthreads();
        if (i + 2 < KITERS) ISSUE_STAGE(i + 2);

        const uint32_t sb = (uint32_t)(i % NSTAGE) * STAGE_BYTES;
#pragma unroll
        for (int kk = 0; kk < 4; kk++) {
            const uint32_t kkb = (uint32_t)kk * 32u;
            uint32_t a[4][4], b[2][4];
#pragma unroll
            for (int mi = 0; mi < 4; mi++)
                LDSM_X4(a[mi][0], a[mi][1], a[mi][2], a[mi][3],
                        addrA[mi] + sb + ((kkb | chunkA) ^ xA[mi]));
#pragma unroll
            for (int np = 0; np < 2; np++)
                LDSM_X4(b[np][0], b[np][1], b[np][2], b[np][3],
                        addrB[np] + sb + ((kkb | chunkB) ^ xB[np]));
#pragma unroll
            for (int mi = 0; mi < 4; mi++)
#pragma unroll
                for (int ni = 0; ni < 4; ni++)
                    MMA16816(acc[mi][ni],
                             a[mi][0], a[mi][1], a[mi][2], a[mi][3],
                             b[ni >> 1][(ni & 1) * 2],
                             b[ni >> 1][(ni & 1) * 2 + 1]);
        }
    }

    // ---- epilogue: exp, positive capture, per-row partial sums ----
    float vr[4][2];
#pragma unroll
    for (int mi = 0; mi < 4; mi++) { vr[mi][0] = 0.f; vr[mi][1] = 0.f; }

#pragma unroll
    for (int mi = 0; mi < 4; mi++) {
#pragma unroll
        for (int ni = 0; ni < 4; ni++) {
#pragma unroll
            for (int e = 0; e < 4; e++) {
                float v = __expf(acc[mi][ni][e] * 10.0f);
                int h = e >> 1;
                vr[mi][h] += v;
                int rowg = r0 + wm * 64 + mi * 16 + h * 8 + (lane >> 2);
                int col = c0 + wn * 32 + ni * 8 + (lane & 3) * 2 + (e & 1);
                if (col == ((rowg + BHALF) & (NROWS - 1))) g_pos[rowg] = v;
            }
        }
    }
    // reduce across the 4 lanes sharing each row (lane&3)
#pragma unroll
    for (int mi = 0; mi < 4; mi++)
#pragma unroll
        for (int h = 0; h < 2; h++) {
            float v = vr[mi][h];
            v += __shfl_xor_sync(0xFFFFFFFFu, v, 1);
            v += __shfl_xor_sync(0xFFFFFFFFu, v, 2);
            vr[mi][h] = v;
        }

    __syncthreads();               // stage buffers dead; reuse smem as red[4][128]
    float* red = (float*)smem;
    if ((lane & 3) == 0) {
#pragma unroll
        for (int mi = 0; mi < 4; mi++)
#pragma unroll
            for (int h = 0; h < 2; h++) {
                int lr = wm * 64 + mi * 16 + h * 8 + (lane >> 2);
                red[wn * 128 + lr] = vr[mi][h];
            }
    }
    __syncthreads();
    if (tid < 128) {
        float t = red[tid] + red[128 + tid] + red[256 + tid] + red[384 + tid];
        g_rs[((size_t)(r0 + tid)) * 64 + bn] = t;
    }
}

// ---------------------------------------------------------------------------
// Kernel 3: loss = sum_r [log(rowsum_r - pos_r) - log(pos_r)] / (N*B)
// ---------------------------------------------------------------------------
__global__ void loss_kernel(float* __restrict__ out) {
    __shared__ float ws[8];
    float s = 0.f;
    for (int r = threadIdx.x; r < NROWS; r += blockDim.x) {
        const float4* p4 = (const float4*)&g_rs[(size_t)r * 64];
        float tot = 0.f;
#pragma unroll
        for (int i = 0; i < 16; i++) {
            float4 q = p4[i];
            tot += (q.x + q.y) + (q.z + q.w);
        }
        float p = g_pos[r];
        s += logf(tot - p) - logf(p);
    }
#pragma unroll
    for (int o = 16; o; o >>= 1) s += __shfl_xor_sync(0xFFFFFFFFu, s, o);
    if ((threadIdx.x & 31) == 0) ws[threadIdx.x >> 5] = s;
    __syncthreads();
    if (threadIdx.x < 8) {
        float v = ws[threadIdx.x];
#pragma unroll
        for (int o = 4; o; o >>= 1) v += __shfl_xor_sync(0xFFu, v, o);
        if (threadIdx.x == 0)
            out[0] = v / ((float)NROWS * (float)BHALF);
    }
}

extern "C" void kernel_launch(void* const* d_in, const int* in_sizes, int n_in,
                              void* d_out, int out_size) {
    const float* z1 = (const float*)d_in[0];
    const float* z2 = (const float*)d_in[1];
    (void)in_sizes; (void)n_in; (void)out_size;

    cudaFuncSetAttribute(gemm_kernel, cudaFuncAttributeMaxDynamicSharedMemorySize,
                         SMEM_TOTAL);

    normalize_kernel<<<NROWS, 128>>>(z1, z2);
    dim3 grid(NROWS / BN, NROWS / BM);
    gemm_kernel<<<grid, 256, SMEM_TOTAL>>>();
    loss_kernel<<<1, 256>>>((float*)d_out);
}

// round 4
// speedup vs baseline: 8.2829x; 1.8394x over previous
#include <cuda_runtime.h>
#include <cuda_bf16.h>
#include <math.h>
#include <stdint.h>

// NT-Xent loss on GB300, HMMA (mma.sync bf16) path with SYMMETRY exploitation:
// S = z z^T is symmetric -> compute only upper-triangle block pairs (2080 of
// 4096 tiles). Off-diagonal tiles contribute row-sums to both their row block
// (directly) and their column block (as column sums). pos[r>=B] = pos[r-B].

#define NROWS 8192
#define NC    512
#define BHALF 4096
#define NB    (NROWS / 128)       // 64 block-tiles per dim
#define NPAIRS (NB * (NB + 1) / 2)  // 2080

#define BM 128
#define BN 128
#define BK 64
#define KITERS (NC / BK)        // 8
#define NSTAGE 3
#define STAGE_BYTES (2 * BM * BK * 2)   // A + B = 32768
#define SMEM_TOTAL (NSTAGE * STAGE_BYTES)  // 98304

__device__ __align__(1024) __nv_bfloat16 g_zn[(size_t)NROWS * NC];
__device__ float g_pos[BHALF];
__device__ float g_rs[(size_t)NROWS * NB];   // [row][other_block] partials

__device__ __forceinline__ uint32_t smem_u32(const void* p) {
    uint32_t a;
    asm("{ .reg .u64 t; cvta.to.shared.u64 t, %1; cvt.u32.u64 %0, t; }"
        : "=r"(a) : "l"(p));
    return a;
}

#define CP_ASYNC16(dst, src) \
    asm volatile("cp.async.cg.shared.global [%0], [%1], 16;" :: "r"(dst), "l"(src) : "memory")
#define CP_COMMIT() asm volatile("cp.async.commit_group;" ::: "memory")

#define LDSM_X4(r0, r1, r2, r3, addr)                                          \
    asm volatile("ldmatrix.sync.aligned.m8n8.x4.shared.b16 {%0,%1,%2,%3}, [%4];" \
                 : "=r"(r0), "=r"(r1), "=r"(r2), "=r"(r3) : "r"(addr))

#define MMA16816(c, a0, a1, a2, a3, b0, b1)                                    \
    asm volatile("mma.sync.aligned.m16n8k16.row.col.f32.bf16.bf16.f32 "        \
                 "{%0,%1,%2,%3},{%4,%5,%6,%7},{%8,%9},{%0,%1,%2,%3};"          \
                 : "+f"((c)[0]), "+f"((c)[1]), "+f"((c)[2]), "+f"((c)[3])      \
                 : "r"(a0), "r"(a1), "r"(a2), "r"(a3), "r"(b0), "r"(b1))

// ---------------------------------------------------------------------------
// Kernel 1: L2-normalize rows, emit bf16 z
// ---------------------------------------------------------------------------
__global__ void normalize_kernel(const float* __restrict__ z1,
                                 const float* __restrict__ z2) {
    int r = blockIdx.x;
    const float* row = (r < BHALF) ? (z1 + (size_t)r * NC)
                                   : (z2 + (size_t)(r - BHALF) * NC);
    int t = threadIdx.x;
    float4 v = ((const float4*)row)[t];
    float s = v.x * v.x + v.y * v.y + v.z * v.z + v.w * v.w;
#pragma unroll
    for (int o = 16; o; o >>= 1) s += __shfl_xor_sync(0xFFFFFFFFu, s, o);
    __shared__ float ws[4];
    if ((t & 31) == 0) ws[t >> 5] = s;
    __syncthreads();
    s = ws[0] + ws[1] + ws[2] + ws[3];
    float inv = 1.0f / fmaxf(sqrtf(s), 1e-12f);
    __nv_bfloat162 lo = __floats2bfloat162_rn(v.x * inv, v.y * inv);
    __nv_bfloat162 hi = __floats2bfloat162_rn(v.z * inv, v.w * inv);
    __nv_bfloat162* dst = (__nv_bfloat162*)g_zn + (size_t)r * (NC / 2) + t * 2;
    dst[0] = lo;
    dst[1] = hi;
}

// ---------------------------------------------------------------------------
// Kernel 2: fused GEMM + exp + row/col sums + positive capture (upper tri).
// 256 threads = 8 warps in 2(M) x 4(N); warp tile 64x32 via m16n8k16.
// ---------------------------------------------------------------------------
__global__ __launch_bounds__(256, 2) void gemm_kernel() {
    extern __shared__ __align__(1024) char smem[];
    const int tid = threadIdx.x;
    const int lane = tid & 31;
    const int w = tid >> 5;
    const int wm = w >> 2;       // 0..1
    const int wn = w & 3;        // 0..3

    // map linear block id -> upper-triangle pair (bm <= bn)
    int rem = blockIdx.x;
    int bm = 0;
#pragma unroll 1
    while (rem >= (NB - bm)) { rem -= (NB - bm); bm++; }
    const int bn = bm + rem;
    const int r0 = bm * BM;
    const int c0 = bn * BN;
    const uint32_t sbase = smem_u32(smem);

    // ---- cp.async mapping: 256 threads -> 256 tile rows (128 A + 128 B) ----
    const int half = tid >> 7;          // 0 = A (rows), 1 = B (cols)
    const int lrow = tid & 127;
    const char* grow = (const char*)g_zn +
        ((size_t)((half ? c0 : r0) + lrow)) * (NC * 2);
    const uint32_t sdst = sbase + (uint32_t)half * (BM * BK * 2) +
                          (uint32_t)lrow * 128u;
    const uint32_t xr = ((uint32_t)lrow & 7u) << 4;

#define ISSUE_STAGE(s_)                                                        \
    do {                                                                       \
        const char* g_ = grow + (s_) * (BK * 2);                               \
        uint32_t d_ = sdst + (uint32_t)((s_) % NSTAGE) * STAGE_BYTES;          \
        _Pragma("unroll")                                                      \
        for (int c_ = 0; c_ < 8; c_++)                                         \
            CP_ASYNC16(d_ + (((uint32_t)c_ * 16u) ^ xr), g_ + c_ * 16);        \
        CP_COMMIT();                                                           \
    } while (0)

    ISSUE_STAGE(0);
    ISSUE_STAGE(1);

    // ---- ldmatrix address precompute ----
    uint32_t addrA[4], xA[4];
    const uint32_t chunkA = ((uint32_t)(lane >> 4)) * 16u;
#pragma unroll
    for (int mi = 0; mi < 4; mi++) {
        int rA = wm * 64 + mi * 16 + (lane & 15);
        addrA[mi] = sbase + (uint32_t)rA * 128u;
        xA[mi] = ((uint32_t)rA & 7u) << 4;
    }
    uint32_t addrB[2], xB[2];
    const uint32_t chunkB = ((uint32_t)((lane >> 3) & 1)) * 16u;
#pragma unroll
    for (int np = 0; np < 2; np++) {
        int rB = wn * 32 + np * 16 + ((lane >> 4) & 1) * 8 + (lane & 7);
        addrB[np] = sbase + (uint32_t)(BM * BK * 2) + (uint32_t)rB * 128u;
        xB[np] = ((uint32_t)rB & 7u) << 4;
    }

    float acc[4][4][4];
#pragma unroll
    for (int mi = 0; mi < 4; mi++)
#pragma unroll
        for (int ni = 0; ni < 4; ni++)
#pragma unroll
            for (int e = 0; e < 4; e++) acc[mi][ni][e] = 0.f;

    // ---- mainloop ----
#pragma unroll 1
    for (int i = 0; i < KITERS; i++) {
        if (i < KITERS - 1)
            asm volatile("cp.async.wait_group 1;" ::: "memory");
        else
            asm volatile("cp.async.wait_group 0;" ::: "memory");
        __syncthreads();
        if (i + 2 < KITERS) ISSUE_STAGE(i + 2);

        const uint32_t sb = (uint32_t)(i % NSTAGE) * STAGE_BYTES;
#pragma unroll
        for (int kk = 0; kk < 4; kk++) {
            const uint32_t kkb = (uint32_t)kk * 32u;
            uint32_t a[4][4], b[2][4];
#pragma unroll
            for (int mi = 0; mi < 4; mi++)
                LDSM_X4(a[mi][0], a[mi][1], a[mi][2], a[mi][3],
                        addrA[mi] + sb + ((kkb | chunkA) ^ xA[mi]));
#pragma unroll
            for (int np = 0; np < 2; np++)
                LDSM_X4(b[np][0], b[np][1], b[np][2], b[np][3],
                        addrB[np] + sb + ((kkb | chunkB) ^ xB[np]));
#pragma unroll
            for (int mi = 0; mi < 4; mi++)
#pragma unroll
                for (int ni = 0; ni < 4; ni++)
                    MMA16816(acc[mi][ni],
                             a[mi][0], a[mi][1], a[mi][2], a[mi][3],
                             b[ni >> 1][(ni & 1) * 2],
                             b[ni >> 1][(ni & 1) * 2 + 1]);
        }
    }

    // ---- epilogue: exp, positive capture, per-row AND per-col partials ----
    float vr[4][2];   // row partials: [mi][half-row]
    float cv[4][2];   // col partials: [ni][e&1]
#pragma unroll
    for (int i = 0; i < 4; i++) {
        vr[i][0] = vr[i][1] = 0.f;
        cv[i][0] = cv[i][1] = 0.f;
    }

#pragma unroll
    for (int mi = 0; mi < 4; mi++) {
#pragma unroll
        for (int ni = 0; ni < 4; ni++) {
#pragma unroll
            for (int e = 0; e < 4; e++) {
                float v = __expf(acc[mi][ni][e] * 10.0f);
                vr[mi][e >> 1] += v;
                cv[ni][e & 1] += v;
                int rowg = r0 + wm * 64 + mi * 16 + (e >> 1) * 8 + (lane >> 2);
                int col = c0 + wn * 32 + ni * 8 + (lane & 3) * 2 + (e & 1);
                if (col == rowg + BHALF) g_pos[rowg] = v;  // fires only for r<B
            }
        }
    }
    // rows: reduce across the 4 lanes sharing each row (lane&3 varies)
#pragma unroll
    for (int mi = 0; mi < 4; mi++)
#pragma unroll
        for (int h = 0; h < 2; h++) {
            float v = vr[mi][h];
            v += __shfl_xor_sync(0xFFFFFFFFu, v, 1);
            v += __shfl_xor_sync(0xFFFFFFFFu, v, 2);
            vr[mi][h] = v;
        }
    // cols: reduce across the 8 lane-groups sharing each col (lane>>2 varies)
#pragma unroll
    for (int ni = 0; ni < 4; ni++)
#pragma unroll
        for (int b = 0; b < 2; b++) {
            float v = cv[ni][b];
            v += __shfl_xor_sync(0xFFFFFFFFu, v, 4);
            v += __shfl_xor_sync(0xFFFFFFFFu, v, 8);
            v += __shfl_xor_sync(0xFFFFFFFFu, v, 16);
            cv[ni][b] = v;
        }

    __syncthreads();               // stage buffers dead; reuse smem
    float* redr = (float*)smem;          // [4 wn][128 rows]
    float* redc = (float*)smem + 512;    // [2 wm][128 cols]
    if ((lane & 3) == 0) {
#pragma unroll
        for (int mi = 0; mi < 4; mi++)
#pragma unroll
            for (int h = 0; h < 2; h++)
                redr[wn * 128 + wm * 64 + mi * 16 + h * 8 + (lane >> 2)] = vr[mi][h];
    }
    if (lane < 4) {
#pragma unroll
        for (int ni = 0; ni < 4; ni++)
#pragma unroll
            for (int b = 0; b < 2; b++)
                redc[wm * 128 + wn * 32 + ni * 8 + lane * 2 + b] = cv[ni][b];
    }
    __syncthreads();
    if (tid < 128) {
        float t = redr[tid] + redr[128 + tid] + redr[256 + tid] + redr[384 + tid];
        g_rs[((size_t)(r0 + tid)) * NB + bn] = t;
    } else if (bm != bn) {
        int t2 = tid - 128;
        float t = redc[t2] + redc[128 + t2];
        g_rs[((size_t)(c0 + t2)) * NB + bm] = t;
    }
}

// ---------------------------------------------------------------------------
// Kernel 3: loss = sum_r [log(rowsum_r - pos_r) - log(pos_r)] / (N*B)
// ---------------------------------------------------------------------------
__global__ void loss_kernel(float* __restrict__ out) {
    __shared__ float ws[8];
    float s = 0.f;
    for (int r = threadIdx.x; r < NROWS; r += blockDim.x) {
        const float4* p4 = (const float4*)&g_rs[(size_t)r * NB];
        float tot = 0.f;
#pragma unroll
        for (int i = 0; i < NB / 4; i++) {
            float4 q = p4[i];
            tot += (q.x + q.y) + (q.z + q.w);
        }
        float p = g_pos[r & (BHALF - 1)];
        s += logf(tot - p) - logf(p);
    }
#pragma unroll
    for (int o = 16; o; o >>= 1) s += __shfl_xor_sync(0xFFFFFFFFu, s, o);
    if ((threadIdx.x & 31) == 0) ws[threadIdx.x >> 5] = s;
    __syncthreads();
    if (threadIdx.x < 8) {
        float v = ws[threadIdx.x];
#pragma unroll
        for (int o = 4; o; o >>= 1) v += __shfl_xor_sync(0xFFu, v, o);
        if (threadIdx.x == 0)
            out[0] = v / ((float)NROWS * (float)BHALF);
    }
}

extern "C" void kernel_launch(void* const* d_in, const int* in_sizes, int n_in,
                              void* d_out, int out_size) {
    const float* z1 = (const float*)d_in[0];
    const float* z2 = (const float*)d_in[1];
    (void)in_sizes; (void)n_in; (void)out_size;

    cudaFuncSetAttribute(gemm_kernel, cudaFuncAttributeMaxDynamicSharedMemorySize,
                         SMEM_TOTAL);

    normalize_kernel<<<NROWS, 128>>>(z1, z2);
    gemm_kernel<<<NPAIRS, 256, SMEM_TOTAL>>>();
    loss_kernel<<<1, 256>>>((float*)d_out);
}